// round 9
// baseline (speedup 1.0000x reference)
#include <cuda_runtime.h>
#include <cuda_bf16.h>
#include <stdint.h>

#define S        128
#define MO       256
#define NROWS    32768       // 2048*16
#define XR       64          // x-rows per CTA
#define NTHREADS 768         // 24 warps

// ---------------- smem layout (bytes) ----------------
#define OFF_A_HI  0          // A: 192 rows x 256B (swizzled), hi
#define OFF_A_LO  49152
#define OFF_B_HI  98304      // B: 128 rows x 256B, hi
#define OFF_B_LO  131072
#define OFF_S_HI  163840     // s tile 64x256B hi
#define OFF_S_LO  180224
#define OFF_G     163840     // gate fp32 64x128 (overlaps S after s consumed)
#define OFF_VN_HI 196608     // vn tile hi
#define OFF_VN_LO 212992
#define OFF_STAGE 196608     // output staging 16x512 f32 (overlaps VN)
#define SMEM_BYTES 229376

// ---------------- weight scratch ----------------
__device__ float g_T[S * S];
__device__ float g_C[S * MO];
__device__ __nv_bfloat16 gWhT_hi[S * S],     gWhT_lo[S * S];      // [n][k]
__device__ __nv_bfloat16 gWuT_hi[S * S],     gWuT_lo[S * S];
__device__ __nv_bfloat16 gWmT_hi[2 * S * S], gWmT_lo[2 * S * S];  // [half][n][k]
__device__ __nv_bfloat16 gCT_hi[MO * S],     gCT_lo[MO * S];      // [n][k]

// ---------------- helpers ----------------
__device__ __forceinline__ uint32_t swoff(int row, int kbyte) {
    return (uint32_t)(row * 256 + ((((kbyte >> 4) ^ (row & 7)) << 4) | (kbyte & 15)));
}
// gate buffer: conflict-free row swizzle (xor multiple-of-4 keeps col pairs)
__device__ __forceinline__ uint32_t gswz(int r, int c) {
    return (uint32_t)(r * 128 + (c ^ ((r & 7) << 2)));
}

__device__ __forceinline__ void ldsm4(uint32_t* r, uint32_t addr) {
    asm volatile("ldmatrix.sync.aligned.m8n8.x4.shared.b16 {%0,%1,%2,%3}, [%4];"
                 : "=r"(r[0]), "=r"(r[1]), "=r"(r[2]), "=r"(r[3]) : "r"(addr));
}

__device__ __forceinline__ void mma16816(float (&d)[4], const uint32_t* a, const uint32_t* b) {
    asm volatile(
        "mma.sync.aligned.m16n8k16.row.col.f32.bf16.bf16.f32 "
        "{%0,%1,%2,%3},{%4,%5,%6,%7},{%8,%9},{%0,%1,%2,%3};"
        : "+f"(d[0]), "+f"(d[1]), "+f"(d[2]), "+f"(d[3])
        : "r"(a[0]), "r"(a[1]), "r"(a[2]), "r"(a[3]), "r"(b[0]), "r"(b[1]));
}

__device__ __forceinline__ uint32_t pack_bf2(__nv_bfloat16 a, __nv_bfloat16 b) {
    return (uint32_t)__bfloat16_as_ushort(a) | ((uint32_t)__bfloat16_as_ushort(b) << 16);
}
__device__ __forceinline__ float2 unpack_bf2(uint32_t u) {
    __nv_bfloat162 b = *reinterpret_cast<__nv_bfloat162*>(&u);
    return make_float2(__bfloat162float(b.x), __bfloat162float(b.y));
}
__device__ __forceinline__ void split2(float a, float b, uint32_t& hi, uint32_t& lo) {
    __nv_bfloat16 ah = __float2bfloat16(a), bh = __float2bfloat16(b);
    __nv_bfloat16 al = __float2bfloat16(a - __bfloat162float(ah));
    __nv_bfloat16 bl = __float2bfloat16(b - __bfloat162float(bh));
    hi = pack_bf2(ah, bh);
    lo = pack_bf2(al, bl);
}

// split-bf16 GEMM: warp tile 16 rows x 64 cols, K=128
__device__ __forceinline__ void gemm16(uint32_t smu,
                                       uint32_t offA_hi, uint32_t offA_lo,
                                       int rbase, int ncol0, int lane,
                                       float (&acc)[8][4], bool zero_init) {
    if (zero_init) {
#pragma unroll
        for (int i = 0; i < 8; i++)
#pragma unroll
            for (int j = 0; j < 4; j++) acc[i][j] = 0.f;
    }
    const int arow   = rbase + (lane & 15);
    const int akoff  = (lane >> 4) * 16;
    const int bn_off = ((lane >> 4) << 3) + (lane & 7);
    const int bkoff  = ((lane >> 3) & 1) * 16;
#pragma unroll
    for (int kc = 0; kc < 8; kc++) {
        uint32_t ah[4], al[4];
        ldsm4(ah, smu + offA_hi + swoff(arow, kc * 32 + akoff));
        ldsm4(al, smu + offA_lo + swoff(arow, kc * 32 + akoff));
#pragma unroll
        for (int jp = 0; jp < 4; jp++) {
            int n = ncol0 + jp * 16 + bn_off;
            uint32_t bh[4], bl[4];
            ldsm4(bh, smu + OFF_B_HI + swoff(n, kc * 32 + bkoff));
            ldsm4(bl, smu + OFF_B_LO + swoff(n, kc * 32 + bkoff));
            mma16816(acc[2 * jp],     ah, &bh[0]);
            mma16816(acc[2 * jp],     ah, &bl[0]);
            mma16816(acc[2 * jp],     al, &bh[0]);
            mma16816(acc[2 * jp + 1], ah, &bh[2]);
            mma16816(acc[2 * jp + 1], ah, &bl[2]);
            mma16816(acc[2 * jp + 1], al, &bh[2]);
        }
    }
}

// gate GEMM: warp tile 16 rows x 32 cols, K=128, accumulate
__device__ __forceinline__ void gate16(uint32_t smu,
                                       uint32_t offA_hi, uint32_t offA_lo,
                                       int rbase, int nbase, int lane,
                                       float (&acc)[4][4]) {
    const int arow   = rbase + (lane & 15);
    const int akoff  = (lane >> 4) * 16;
    const int bn_off = ((lane >> 4) << 3) + (lane & 7);
    const int bkoff  = ((lane >> 3) & 1) * 16;
#pragma unroll
    for (int kc = 0; kc < 8; kc++) {
        uint32_t ah[4], al[4];
        ldsm4(ah, smu + offA_hi + swoff(arow, kc * 32 + akoff));
        ldsm4(al, smu + offA_lo + swoff(arow, kc * 32 + akoff));
#pragma unroll
        for (int jp = 0; jp < 2; jp++) {
            int n = nbase + jp * 16 + bn_off;
            uint32_t bh[4], bl[4];
            ldsm4(bh, smu + OFF_B_HI + swoff(n, kc * 32 + bkoff));
            ldsm4(bl, smu + OFF_B_LO + swoff(n, kc * 32 + bkoff));
            mma16816(acc[2 * jp],     ah, &bh[0]);
            mma16816(acc[2 * jp],     ah, &bl[0]);
            mma16816(acc[2 * jp],     al, &bh[0]);
            mma16816(acc[2 * jp + 1], ah, &bh[2]);
            mma16816(acc[2 * jp + 1], ah, &bl[2]);
            mma16816(acc[2 * jp + 1], al, &bh[2]);
        }
    }
}

__device__ __forceinline__ void load_B(char* smem,
                                       const __nv_bfloat16* __restrict__ gh,
                                       const __nv_bfloat16* __restrict__ gl, int tid) {
    for (int i = tid; i < 2048; i += NTHREADS) {
        int r = i >> 4, c = i & 15;
        uint32_t d = r * 256 + (((c ^ (r & 7))) << 4);
        *(uint4*)(smem + OFF_B_HI + d) = *(const uint4*)(gh + r * 128 + c * 8);
        *(uint4*)(smem + OFF_B_LO + d) = *(const uint4*)(gl + r * 128 + c * 8);
    }
}

// ---------------- weight prep ----------------
__global__ void prep_T(const float* __restrict__ Wh1, const float* __restrict__ Wu1) {
    int m = blockIdx.x, o = threadIdx.x;
    float acc = 0.f;
#pragma unroll 8
    for (int h = 0; h < S; h++)
        acc = fmaf(__ldg(&Wh1[m * S + h]), __ldg(&Wu1[h * S + o]), acc);
    g_T[m * S + o] = acc;
}

__global__ void prep_C(const float* __restrict__ W1) {
    int m = blockIdx.x, n = threadIdx.x;
    float acc = 0.f;
#pragma unroll 8
    for (int o = 0; o < S; o++)
        acc = fmaf(g_T[m * S + o], __ldg(&W1[o * MO + n]), acc);
    g_C[m * MO + n] = acc * 0.08838834764831845f;  // 1/sqrt(128)
}

__global__ void pack_w(const float* __restrict__ Wh0, const float* __restrict__ Wu0,
                       const float* __restrict__ Wm0) {
    int i = blockIdx.x * 256 + threadIdx.x;   // 98304 total
    float v;
    __nv_bfloat16 *dh, *dl;
    int pos;
    if (i < 16384) {
        int n = i >> 7, k = i & 127;
        v = Wh0[k * S + n]; dh = gWhT_hi; dl = gWhT_lo; pos = i;
    } else if (i < 32768) {
        int j = i - 16384; int n = j >> 7, k = j & 127;
        v = Wu0[k * S + n]; dh = gWuT_hi; dl = gWuT_lo; pos = j;
    } else if (i < 65536) {
        int j = i - 32768; int half = j >> 14, n = (j >> 7) & 127, k = j & 127;
        v = Wm0[(half * S + k) * S + n]; dh = gWmT_hi; dl = gWmT_lo; pos = j;
    } else {
        int j = i - 65536; int n = j >> 7, k = j & 127;
        v = g_C[k * MO + n]; dh = gCT_hi; dl = gCT_lo; pos = j;
    }
    __nv_bfloat16 h = __float2bfloat16(v);
    dh[pos] = h;
    dl[pos] = __float2bfloat16(v - __bfloat162float(h));
}

// ---------------- the fused kernel ----------------
__global__ void __launch_bounds__(NTHREADS, 1) fused(
    const float* __restrict__ x,
    const float* __restrict__ bm0,
    float* __restrict__ out)
{
    extern __shared__ char smem[];
    const uint32_t smu = (uint32_t)__cvta_generic_to_shared(smem);
    const int tid  = threadIdx.x;
    const int wid  = tid >> 5;
    const int lane = tid & 31;
    const int row0 = blockIdx.x * XR;
    float* gptr = (float*)(smem + OFF_G);
    float* stg  = (float*)(smem + OFF_STAGE);

    // ===== phase 0: pack input (vectorized) =====
    for (int p = tid; p < XR * 32; p += NTHREADS) {                // s: float4
        int row = p >> 5, c4 = (p & 31) << 2;
        float4 f = *(const float4*)(x + (size_t)(row0 + row) * 512 + c4);
        uint32_t hi, lo;
        uint32_t d = swoff(row, c4 * 2);
        split2(f.x, f.y, hi, lo);
        *(uint32_t*)(smem + OFF_S_HI + d) = hi;
        *(uint32_t*)(smem + OFF_S_LO + d) = lo;
        split2(f.z, f.w, hi, lo);
        *(uint32_t*)(smem + OFF_S_HI + d + 4) = hi;
        *(uint32_t*)(smem + OFF_S_LO + d + 4) = lo;
    }
    for (int q = tid; q < XR * 96; q += NTHREADS) {                // v: float4
        int xr = q / 96, f4 = q - xr * 96;
        float4 f = *(const float4*)(x + (size_t)(row0 + xr) * 512 + 128 + f4 * 4);
        float vals[4] = {f.x, f.y, f.z, f.w};
#pragma unroll
        for (int e = 0; e < 4; e++) {
            int j = f4 * 4 + e;
            int m = (j * 21846) >> 16;   // j/3
            int t = j - 3 * m;
            __nv_bfloat16 h = __float2bfloat16(vals[e]);
            __nv_bfloat16 l = __float2bfloat16(vals[e] - __bfloat162float(h));
            uint32_t d = swoff(t * 64 + xr, m * 2);
            *(uint16_t*)(smem + OFF_A_HI + d) = __bfloat16_as_ushort(h);
            *(uint16_t*)(smem + OFF_A_LO + d) = __bfloat16_as_ushort(l);
        }
    }
    load_B(smem, gWhT_hi, gWhT_lo, tid);
    __syncthreads();

    float acc[8][4];
    const int rbase = (wid >> 1) * 16;      // 0..184
    const int ncol0 = (wid & 1) * 64;
    const int tcomp = wid >> 3;             // t component of this warp's rows
    const int r0 = rbase + (lane >> 2), r1 = r0 + 8;
    const int xr0 = r0 & 63, xr1 = r1 & 63;

    // ===== phase 1: Vh = v @ Wh0 =====
    gemm16(smu, OFF_A_HI, OFF_A_LO, rbase, ncol0, lane, acc, true);
    __syncthreads();                        // all A/B reads done
#pragma unroll
    for (int i = 0; i < 8; i++) {
        int c = ncol0 + i * 8 + (lane & 3) * 2;
        uint32_t hi, lo;
        split2(acc[i][0], acc[i][1], hi, lo);
        uint32_t d0 = swoff(r0, c * 2);
        *(uint32_t*)(smem + OFF_A_HI + d0) = hi;
        *(uint32_t*)(smem + OFF_A_LO + d0) = lo;
        split2(acc[i][2], acc[i][3], hi, lo);
        uint32_t d1 = swoff(r1, c * 2);
        *(uint32_t*)(smem + OFF_A_HI + d1) = hi;
        *(uint32_t*)(smem + OFF_A_LO + d1) = lo;
    }
    load_B(smem, gWmT_hi, gWmT_lo, tid);    // Wm half 0
    __syncthreads();

    // ===== phase 2: vn = sqrt(sum_t Vh^2 + eps) =====
    for (int p = tid; p < XR * 64; p += NTHREADS) {
        int xr = p >> 6, h2 = (p & 63) << 1;
        float s0 = 1e-8f, s1 = 1e-8f;
#pragma unroll
        for (int t = 0; t < 3; t++) {
            uint32_t d = swoff(t * 64 + xr, h2 * 2);
            float2 fh = unpack_bf2(*(uint32_t*)(smem + OFF_A_HI + d));
            float2 fl = unpack_bf2(*(uint32_t*)(smem + OFF_A_LO + d));
            float x0 = fh.x + fl.x, x1 = fh.y + fl.y;
            s0 = fmaf(x0, x0, s0);
            s1 = fmaf(x1, x1, s1);
        }
        uint32_t hi, lo; split2(sqrtf(s0), sqrtf(s1), hi, lo);
        uint32_t d = swoff(xr, h2 * 2);
        *(uint32_t*)(smem + OFF_VN_HI + d) = hi;
        *(uint32_t*)(smem + OFF_VN_LO + d) = lo;
    }
    __syncthreads();

    // ===== phase 3: gate = sigmoid([s,vn] @ Wm0 + bm0)  (warps 0-15, 16x32 tiles) =====
    float acc2[4][4];
#pragma unroll
    for (int i = 0; i < 4; i++)
#pragma unroll
        for (int j = 0; j < 4; j++) acc2[i][j] = 0.f;
    const int grb = (wid & 3) * 16;
    const int gnb = ((wid >> 2) & 3) * 32;
    if (wid < 16)
        gate16(smu, OFF_S_HI, OFF_S_LO, grb, gnb, lane, acc2);
    __syncthreads();
    load_B(smem, gWmT_hi + 16384, gWmT_lo + 16384, tid);   // Wm half 1
    __syncthreads();
    if (wid < 16)
        gate16(smu, OFF_VN_HI, OFF_VN_LO, grb, gnb, lane, acc2);
    __syncthreads();                        // s-region reads long done; safe to write g
    if (wid < 16) {
        int gr0 = grb + (lane >> 2), gr1 = gr0 + 8;
#pragma unroll
        for (int i = 0; i < 4; i++) {
            int n = gnb + i * 8 + (lane & 3) * 2;
            float b0 = __ldg(&bm0[n]), b1 = __ldg(&bm0[n + 1]);
            gptr[gswz(gr0, n)]     = 1.f / (1.f + __expf(-(acc2[i][0] + b0)));
            gptr[gswz(gr0, n + 1)] = 1.f / (1.f + __expf(-(acc2[i][1] + b1)));
            gptr[gswz(gr1, n)]     = 1.f / (1.f + __expf(-(acc2[i][2] + b0)));
            gptr[gswz(gr1, n + 1)] = 1.f / (1.f + __expf(-(acc2[i][3] + b1)));
        }
    }
    load_B(smem, gWuT_hi, gWuT_lo, tid);
    __syncthreads();

    // ===== phase 4: v1 = (Vh @ Wu0) * g =====
    gemm16(smu, OFF_A_HI, OFF_A_LO, rbase, ncol0, lane, acc, true);
    __syncthreads();
#pragma unroll
    for (int i = 0; i < 8; i++) {
        int c = ncol0 + i * 8 + (lane & 3) * 2;
        float g00 = gptr[gswz(xr0, c)], g01 = gptr[gswz(xr0, c + 1)];
        float g10 = gptr[gswz(xr1, c)], g11 = gptr[gswz(xr1, c + 1)];
        uint32_t hi, lo;
        split2(acc[i][0] * g00, acc[i][1] * g01, hi, lo);
        uint32_t d0 = swoff(r0, c * 2);
        *(uint32_t*)(smem + OFF_A_HI + d0) = hi;
        *(uint32_t*)(smem + OFF_A_LO + d0) = lo;
        split2(acc[i][2] * g10, acc[i][3] * g11, hi, lo);
        uint32_t d1 = swoff(r1, c * 2);
        *(uint32_t*)(smem + OFF_A_HI + d1) = hi;
        *(uint32_t*)(smem + OFF_A_LO + d1) = lo;
    }
    load_B(smem, gCT_hi, gCT_lo, tid);      // C half 0
    __syncthreads();

    // ===== phase 5: vo = v1 @ C (two N-halves), staged coalesced output =====
    const int myslice = (rbase >> 4) & 3;   // 16-row slice of xr this warp owns
#pragma unroll 1
    for (int nh = 0; nh < 2; nh++) {
        gemm16(smu, OFF_A_HI, OFF_A_LO, rbase, ncol0, lane, acc, true);
#pragma unroll 1
        for (int slice = 0; slice < 4; slice++) {
            __syncthreads();                // staging free / previous flush done
            if (myslice == slice) {
                int rl0 = lane >> 2, rl1 = rl0 + 8;     // r&15
#pragma unroll
                for (int i = 0; i < 8; i++) {
                    int c  = ncol0 + i * 8 + (lane & 3) * 2;
                    int fl = c >> 4, nl = c & 15;
                    int p0 = fl * 64 + 16 + nl * 3 + tcomp;
                    int p1 = fl * 64 + 16 + (nl + 1) * 3 + tcomp;
                    stg[rl0 * 512 + (p0 ^ ((rl0 & 7) << 2))] = acc[i][0];
                    stg[rl0 * 512 + (p1 ^ ((rl0 & 7) << 2))] = acc[i][1];
                    stg[rl1 * 512 + (p0 ^ ((rl1 & 7) << 2))] = acc[i][2];
                    stg[rl1 * 512 + (p1 ^ ((rl1 & 7) << 2))] = acc[i][3];
                }
            }
            __syncthreads();
            for (int i = tid; i < 2048; i += NTHREADS) {
                int xl = i >> 7, posq = (i & 127) << 2;
                float4 v;
                if ((posq & 63) < 16) v = make_float4(0.f, 0.f, 0.f, 0.f);  // scalar: exact cancel
                else                  v = *(float4*)&stg[xl * 512 + (posq ^ ((xl & 7) << 2))];
                *(float4*)&out[(size_t)(row0 + slice * 16 + xl) * 1024 + nh * 512 + posq] = v;
            }
        }
        if (nh == 0) {
            __syncthreads();
            load_B(smem, gCT_hi + 128 * 128, gCT_lo + 128 * 128, tid);  // C half 1
            __syncthreads();
        }
    }
}

// ---------------- launch ----------------
extern "C" void kernel_launch(void* const* d_in, const int* in_sizes, int n_in,
                              void* d_out, int out_size) {
    const float* x   = (const float*)d_in[0];
    const float* Wh0 = (const float*)d_in[1];
    const float* Wu0 = (const float*)d_in[2];
    const float* Wm0 = (const float*)d_in[3];
    const float* bm0 = (const float*)d_in[4];
    const float* Wh1 = (const float*)d_in[5];
    const float* Wu1 = (const float*)d_in[6];
    // d_in[7]=Wm1, d_in[8]=bm1, d_in[9]=W0 provably unused (scalar channel cancels)
    const float* W1  = (const float*)d_in[10];
    float* out = (float*)d_out;

    cudaFuncSetAttribute(fused, cudaFuncAttributeMaxDynamicSharedMemorySize, SMEM_BYTES);

    prep_T<<<S, S>>>(Wh1, Wu1);
    prep_C<<<S, MO>>>(W1);
    pack_w<<<384, 256>>>(Wh0, Wu0, Wm0);
    fused<<<NROWS / XR, NTHREADS, SMEM_BYTES>>>(x, bm0, out);
}

// round 10
// speedup vs baseline: 1.0038x; 1.0038x over previous
#include <cuda_runtime.h>
#include <cuda_bf16.h>
#include <stdint.h>

#define S        128
#define MO       256
#define NROWS    32768       // 2048*16
#define XR       64          // x-rows per CTA
#define NTHREADS 768         // 24 warps

// ---------------- smem layout (bytes) ----------------
#define OFF_A_HI  0          // A: 192 rows x 256B (swizzled), hi
#define OFF_A_LO  49152
#define OFF_B_HI  98304      // B: 128 rows x 256B, hi
#define OFF_B_LO  131072
#define OFF_S_HI  163840     // s tile 64x256B hi
#define OFF_S_LO  180224
#define OFF_G     163840     // gate fp32 64x128 (overlaps S after s consumed)
#define OFF_VN_HI 196608     // vn tile hi
#define OFF_VN_LO 212992
#define OFF_STAGE 163840     // output staging 32x512 f32 = 64KB (overlaps G+VN, used last)
#define SMEM_BYTES 229376

// ---------------- weight scratch ----------------
__device__ float g_T[S * S];
__device__ float g_C[S * MO];
__device__ __nv_bfloat16 gWhT_hi[S * S],     gWhT_lo[S * S];      // [n][k]
__device__ __nv_bfloat16 gWuT_hi[S * S],     gWuT_lo[S * S];
__device__ __nv_bfloat16 gWmT_hi[2 * S * S], gWmT_lo[2 * S * S];  // [half][n][k]
__device__ __nv_bfloat16 gCT_hi[MO * S],     gCT_lo[MO * S];      // [n][k]

// ---------------- helpers ----------------
__device__ __forceinline__ uint32_t swoff(int row, int kbyte) {
    return (uint32_t)(row * 256 + ((((kbyte >> 4) ^ (row & 7)) << 4) | (kbyte & 15)));
}
__device__ __forceinline__ uint32_t gswz(int r, int c) {
    return (uint32_t)(r * 128 + (c ^ ((r & 7) << 2)));
}

__device__ __forceinline__ void ldsm4(uint32_t* r, uint32_t addr) {
    asm volatile("ldmatrix.sync.aligned.m8n8.x4.shared.b16 {%0,%1,%2,%3}, [%4];"
                 : "=r"(r[0]), "=r"(r[1]), "=r"(r[2]), "=r"(r[3]) : "r"(addr));
}

__device__ __forceinline__ void mma16816(float (&d)[4], const uint32_t* a, const uint32_t* b) {
    asm volatile(
        "mma.sync.aligned.m16n8k16.row.col.f32.bf16.bf16.f32 "
        "{%0,%1,%2,%3},{%4,%5,%6,%7},{%8,%9},{%0,%1,%2,%3};"
        : "+f"(d[0]), "+f"(d[1]), "+f"(d[2]), "+f"(d[3])
        : "r"(a[0]), "r"(a[1]), "r"(a[2]), "r"(a[3]), "r"(b[0]), "r"(b[1]));
}

__device__ __forceinline__ uint32_t pack_bf2(__nv_bfloat16 a, __nv_bfloat16 b) {
    return (uint32_t)__bfloat16_as_ushort(a) | ((uint32_t)__bfloat16_as_ushort(b) << 16);
}
__device__ __forceinline__ float2 unpack_bf2(uint32_t u) {
    __nv_bfloat162 b = *reinterpret_cast<__nv_bfloat162*>(&u);
    return make_float2(__bfloat162float(b.x), __bfloat162float(b.y));
}
__device__ __forceinline__ void split2(float a, float b, uint32_t& hi, uint32_t& lo) {
    __nv_bfloat16 ah = __float2bfloat16(a), bh = __float2bfloat16(b);
    __nv_bfloat16 al = __float2bfloat16(a - __bfloat162float(ah));
    __nv_bfloat16 bl = __float2bfloat16(b - __bfloat162float(bh));
    hi = pack_bf2(ah, bh);
    lo = pack_bf2(al, bl);
}

// split-bf16 GEMM: warp tile 32 rows x 32 cols, K=128.
// acc[q][4], q = rc*4 + np : rc = 16-row chunk (0/1), np = n8 tile (0..3).
__device__ __forceinline__ void gemm32(uint32_t smu,
                                       uint32_t offA_hi, uint32_t offA_lo,
                                       int rbase, int ncol0, int lane,
                                       float (&acc)[8][4], bool zero_init) {
    if (zero_init) {
#pragma unroll
        for (int i = 0; i < 8; i++)
#pragma unroll
            for (int j = 0; j < 4; j++) acc[i][j] = 0.f;
    }
    const int arow0 = rbase + (lane & 15);
    const int arow1 = arow0 + 16;
    const int akoff = (lane >> 4) * 16;
    const int bn0   = ncol0 + ((lane >> 4) << 3) + (lane & 7);
    const int bn1   = bn0 + 16;
    const int bkoff = ((lane >> 3) & 1) * 16;
#pragma unroll
    for (int kc = 0; kc < 8; kc++) {
        const int kb_a = kc * 32 + akoff;
        const int kb_b = kc * 32 + bkoff;
        uint32_t bh0[4], bh1[4], bl0[4], bl1[4];
        uint32_t ah0[4], ah1[4], al0[4], al1[4];
        ldsm4(bh0, smu + OFF_B_HI + swoff(bn0,   kb_b));
        ldsm4(bh1, smu + OFF_B_HI + swoff(bn1,   kb_b));
        ldsm4(ah0, smu + offA_hi + swoff(arow0, kb_a));
        ldsm4(ah1, smu + offA_hi + swoff(arow1, kb_a));
        ldsm4(bl0, smu + OFF_B_LO + swoff(bn0,   kb_b));
        ldsm4(bl1, smu + OFF_B_LO + swoff(bn1,   kb_b));
        ldsm4(al0, smu + offA_lo + swoff(arow0, kb_a));
        ldsm4(al1, smu + offA_lo + swoff(arow1, kb_a));
        // hi*hi (8 independent chains)
        mma16816(acc[0], ah0, &bh0[0]);
        mma16816(acc[1], ah0, &bh0[2]);
        mma16816(acc[2], ah0, &bh1[0]);
        mma16816(acc[3], ah0, &bh1[2]);
        mma16816(acc[4], ah1, &bh0[0]);
        mma16816(acc[5], ah1, &bh0[2]);
        mma16816(acc[6], ah1, &bh1[0]);
        mma16816(acc[7], ah1, &bh1[2]);
        // hi*lo
        mma16816(acc[0], ah0, &bl0[0]);
        mma16816(acc[1], ah0, &bl0[2]);
        mma16816(acc[2], ah0, &bl1[0]);
        mma16816(acc[3], ah0, &bl1[2]);
        mma16816(acc[4], ah1, &bl0[0]);
        mma16816(acc[5], ah1, &bl0[2]);
        mma16816(acc[6], ah1, &bl1[0]);
        mma16816(acc[7], ah1, &bl1[2]);
        // lo*hi
        mma16816(acc[0], al0, &bh0[0]);
        mma16816(acc[1], al0, &bh0[2]);
        mma16816(acc[2], al0, &bh1[0]);
        mma16816(acc[3], al0, &bh1[2]);
        mma16816(acc[4], al1, &bh0[0]);
        mma16816(acc[5], al1, &bh0[2]);
        mma16816(acc[6], al1, &bh1[0]);
        mma16816(acc[7], al1, &bh1[2]);
    }
}

// gate GEMM: warp tile 16 rows x 32 cols, K=128, accumulate
__device__ __forceinline__ void gate16(uint32_t smu,
                                       uint32_t offA_hi, uint32_t offA_lo,
                                       int rbase, int nbase, int lane,
                                       float (&acc)[4][4]) {
    const int arow   = rbase + (lane & 15);
    const int akoff  = (lane >> 4) * 16;
    const int bn_off = ((lane >> 4) << 3) + (lane & 7);
    const int bkoff  = ((lane >> 3) & 1) * 16;
#pragma unroll
    for (int kc = 0; kc < 8; kc++) {
        uint32_t ah[4], al[4];
        ldsm4(ah, smu + offA_hi + swoff(arow, kc * 32 + akoff));
        ldsm4(al, smu + offA_lo + swoff(arow, kc * 32 + akoff));
#pragma unroll
        for (int jp = 0; jp < 2; jp++) {
            int n = nbase + jp * 16 + bn_off;
            uint32_t bh[4], bl[4];
            ldsm4(bh, smu + OFF_B_HI + swoff(n, kc * 32 + bkoff));
            ldsm4(bl, smu + OFF_B_LO + swoff(n, kc * 32 + bkoff));
            mma16816(acc[2 * jp],     ah, &bh[0]);
            mma16816(acc[2 * jp],     ah, &bl[0]);
            mma16816(acc[2 * jp],     al, &bh[0]);
            mma16816(acc[2 * jp + 1], ah, &bh[2]);
            mma16816(acc[2 * jp + 1], ah, &bl[2]);
            mma16816(acc[2 * jp + 1], al, &bh[2]);
        }
    }
}

__device__ __forceinline__ void load_B(char* smem,
                                       const __nv_bfloat16* __restrict__ gh,
                                       const __nv_bfloat16* __restrict__ gl, int tid) {
    for (int i = tid; i < 2048; i += NTHREADS) {
        int r = i >> 4, c = i & 15;
        uint32_t d = r * 256 + (((c ^ (r & 7))) << 4);
        *(uint4*)(smem + OFF_B_HI + d) = *(const uint4*)(gh + r * 128 + c * 8);
        *(uint4*)(smem + OFF_B_LO + d) = *(const uint4*)(gl + r * 128 + c * 8);
    }
}

// ---------------- weight prep ----------------
__global__ void prep_T(const float* __restrict__ Wh1, const float* __restrict__ Wu1) {
    int m = blockIdx.x, o = threadIdx.x;
    float acc = 0.f;
#pragma unroll 8
    for (int h = 0; h < S; h++)
        acc = fmaf(__ldg(&Wh1[m * S + h]), __ldg(&Wu1[h * S + o]), acc);
    g_T[m * S + o] = acc;
}

__global__ void prep_C(const float* __restrict__ W1) {
    int m = blockIdx.x, n = threadIdx.x;
    float acc = 0.f;
#pragma unroll 8
    for (int o = 0; o < S; o++)
        acc = fmaf(g_T[m * S + o], __ldg(&W1[o * MO + n]), acc);
    g_C[m * MO + n] = acc * 0.08838834764831845f;  // 1/sqrt(128)
}

__global__ void pack_w(const float* __restrict__ Wh0, const float* __restrict__ Wu0,
                       const float* __restrict__ Wm0) {
    int i = blockIdx.x * 256 + threadIdx.x;   // 98304 total
    float v;
    __nv_bfloat16 *dh, *dl;
    int pos;
    if (i < 16384) {
        int n = i >> 7, k = i & 127;
        v = Wh0[k * S + n]; dh = gWhT_hi; dl = gWhT_lo; pos = i;
    } else if (i < 32768) {
        int j = i - 16384; int n = j >> 7, k = j & 127;
        v = Wu0[k * S + n]; dh = gWuT_hi; dl = gWuT_lo; pos = j;
    } else if (i < 65536) {
        int j = i - 32768; int half = j >> 14, n = (j >> 7) & 127, k = j & 127;
        v = Wm0[(half * S + k) * S + n]; dh = gWmT_hi; dl = gWmT_lo; pos = j;
    } else {
        int j = i - 65536; int n = j >> 7, k = j & 127;
        v = g_C[k * MO + n]; dh = gCT_hi; dl = gCT_lo; pos = j;
    }
    __nv_bfloat16 h = __float2bfloat16(v);
    dh[pos] = h;
    dl[pos] = __float2bfloat16(v - __bfloat162float(h));
}

// ---------------- the fused kernel ----------------
__global__ void __launch_bounds__(NTHREADS, 1) fused(
    const float* __restrict__ x,
    const float* __restrict__ bm0,
    float* __restrict__ out)
{
    extern __shared__ char smem[];
    const uint32_t smu = (uint32_t)__cvta_generic_to_shared(smem);
    const int tid  = threadIdx.x;
    const int wid  = tid >> 5;
    const int lane = tid & 31;
    const int row0 = blockIdx.x * XR;
    float* gptr = (float*)(smem + OFF_G);
    float* stg  = (float*)(smem + OFF_STAGE);

    // ===== phase 0: pack input (vectorized); kick off B(Wh) LDGs first =====
    load_B(smem, gWhT_hi, gWhT_lo, tid);
    for (int p = tid; p < XR * 32; p += NTHREADS) {                // s: float4
        int row = p >> 5, c4 = (p & 31) << 2;
        float4 f = *(const float4*)(x + (size_t)(row0 + row) * 512 + c4);
        uint32_t hi, lo;
        uint32_t d = swoff(row, c4 * 2);
        split2(f.x, f.y, hi, lo);
        *(uint32_t*)(smem + OFF_S_HI + d) = hi;
        *(uint32_t*)(smem + OFF_S_LO + d) = lo;
        split2(f.z, f.w, hi, lo);
        *(uint32_t*)(smem + OFF_S_HI + d + 4) = hi;
        *(uint32_t*)(smem + OFF_S_LO + d + 4) = lo;
    }
    for (int q = tid; q < XR * 96; q += NTHREADS) {                // v: float4
        int xr = q / 96, f4 = q - xr * 96;
        float4 f = *(const float4*)(x + (size_t)(row0 + xr) * 512 + 128 + f4 * 4);
        float vals[4] = {f.x, f.y, f.z, f.w};
#pragma unroll
        for (int e = 0; e < 4; e++) {
            int j = f4 * 4 + e;
            int m = (j * 21846) >> 16;   // j/3
            int t = j - 3 * m;
            __nv_bfloat16 h = __float2bfloat16(vals[e]);
            __nv_bfloat16 l = __float2bfloat16(vals[e] - __bfloat162float(h));
            uint32_t d = swoff(t * 64 + xr, m * 2);
            *(uint16_t*)(smem + OFF_A_HI + d) = __bfloat16_as_ushort(h);
            *(uint16_t*)(smem + OFF_A_LO + d) = __bfloat16_as_ushort(l);
        }
    }
    __syncthreads();

    float acc[8][4];
    const int rbase = (wid >> 2) * 32;      // 0..160 (6 row strips of 32)
    const int ncol0 = (wid & 3) * 32;       // 4 col strips of 32
    const int tcomp = wid >> 3;             // t component of this warp's rows
    const int rA    = rbase + (lane >> 2);  // +0/+8 (j), +16 (rc)

    // ===== phase 1: Vh = v @ Wh0 =====
    gemm32(smu, OFF_A_HI, OFF_A_LO, rbase, ncol0, lane, acc, true);
    __syncthreads();                        // all A/B reads done
#pragma unroll
    for (int q = 0; q < 8; q++) {
        int rc = q >> 2, np = q & 3;
        int c  = ncol0 + np * 8 + (lane & 3) * 2;
        int ra = rA + rc * 16;
        uint32_t hi, lo;
        split2(acc[q][0], acc[q][1], hi, lo);
        uint32_t d0 = swoff(ra, c * 2);
        *(uint32_t*)(smem + OFF_A_HI + d0) = hi;
        *(uint32_t*)(smem + OFF_A_LO + d0) = lo;
        split2(acc[q][2], acc[q][3], hi, lo);
        uint32_t d1 = swoff(ra + 8, c * 2);
        *(uint32_t*)(smem + OFF_A_HI + d1) = hi;
        *(uint32_t*)(smem + OFF_A_LO + d1) = lo;
    }
    load_B(smem, gWmT_hi, gWmT_lo, tid);    // Wm half 0
    __syncthreads();

    // ===== phase 2: vn = sqrt(sum_t Vh^2 + eps) =====
    for (int p = tid; p < XR * 64; p += NTHREADS) {
        int xr = p >> 6, h2 = (p & 63) << 1;
        float s0 = 1e-8f, s1 = 1e-8f;
#pragma unroll
        for (int t = 0; t < 3; t++) {
            uint32_t d = swoff(t * 64 + xr, h2 * 2);
            float2 fh = unpack_bf2(*(uint32_t*)(smem + OFF_A_HI + d));
            float2 fl = unpack_bf2(*(uint32_t*)(smem + OFF_A_LO + d));
            float x0 = fh.x + fl.x, x1 = fh.y + fl.y;
            s0 = fmaf(x0, x0, s0);
            s1 = fmaf(x1, x1, s1);
        }
        uint32_t hi, lo; split2(sqrtf(s0), sqrtf(s1), hi, lo);
        uint32_t d = swoff(xr, h2 * 2);
        *(uint32_t*)(smem + OFF_VN_HI + d) = hi;
        *(uint32_t*)(smem + OFF_VN_LO + d) = lo;
    }
    __syncthreads();

    // ===== phase 3: gate = sigmoid([s,vn] @ Wm0 + bm0)  (warps 0-15, 16x32 tiles) =====
    float acc2[4][4];
#pragma unroll
    for (int i = 0; i < 4; i++)
#pragma unroll
        for (int j = 0; j < 4; j++) acc2[i][j] = 0.f;
    const int grb = (wid & 3) * 16;
    const int gnb = ((wid >> 2) & 3) * 32;
    if (wid < 16)
        gate16(smu, OFF_S_HI, OFF_S_LO, grb, gnb, lane, acc2);
    __syncthreads();
    load_B(smem, gWmT_hi + 16384, gWmT_lo + 16384, tid);   // Wm half 1
    __syncthreads();
    if (wid < 16)
        gate16(smu, OFF_VN_HI, OFF_VN_LO, grb, gnb, lane, acc2);
    __syncthreads();                        // s-region reads done; safe to write g
    if (wid < 16) {
        int gr0 = grb + (lane >> 2), gr1 = gr0 + 8;
#pragma unroll
        for (int i = 0; i < 4; i++) {
            int n = gnb + i * 8 + (lane & 3) * 2;
            float b0 = __ldg(&bm0[n]), b1 = __ldg(&bm0[n + 1]);
            gptr[gswz(gr0, n)]     = 1.f / (1.f + __expf(-(acc2[i][0] + b0)));
            gptr[gswz(gr0, n + 1)] = 1.f / (1.f + __expf(-(acc2[i][1] + b1)));
            gptr[gswz(gr1, n)]     = 1.f / (1.f + __expf(-(acc2[i][2] + b0)));
            gptr[gswz(gr1, n + 1)] = 1.f / (1.f + __expf(-(acc2[i][3] + b1)));
        }
    }
    load_B(smem, gWuT_hi, gWuT_lo, tid);
    __syncthreads();

    // ===== phase 4: v1 = (Vh @ Wu0) * g =====
    gemm32(smu, OFF_A_HI, OFF_A_LO, rbase, ncol0, lane, acc, true);
    __syncthreads();
#pragma unroll
    for (int q = 0; q < 8; q++) {
        int rc = q >> 2, np = q & 3;
        int c  = ncol0 + np * 8 + (lane & 3) * 2;
        int ra = rA + rc * 16;
        int xa = ra & 63, xb = (ra + 8) & 63;
        float g00 = gptr[gswz(xa, c)], g01 = gptr[gswz(xa, c + 1)];
        float g10 = gptr[gswz(xb, c)], g11 = gptr[gswz(xb, c + 1)];
        uint32_t hi, lo;
        split2(acc[q][0] * g00, acc[q][1] * g01, hi, lo);
        uint32_t d0 = swoff(ra, c * 2);
        *(uint32_t*)(smem + OFF_A_HI + d0) = hi;
        *(uint32_t*)(smem + OFF_A_LO + d0) = lo;
        split2(acc[q][2] * g10, acc[q][3] * g11, hi, lo);
        uint32_t d1 = swoff(ra + 8, c * 2);
        *(uint32_t*)(smem + OFF_A_HI + d1) = hi;
        *(uint32_t*)(smem + OFF_A_LO + d1) = lo;
    }
    load_B(smem, gCT_hi, gCT_lo, tid);      // C half 0
    __syncthreads();

    // ===== phase 5: vo = v1 @ C (two N-halves), 32-row staged coalesced output =====
    const int myslice = (rbase >> 5) & 1;   // 32-row slice of xr this warp owns
#pragma unroll 1
    for (int nh = 0; nh < 2; nh++) {
        gemm32(smu, OFF_A_HI, OFF_A_LO, rbase, ncol0, lane, acc, true);
#pragma unroll 1
        for (int slice = 0; slice < 2; slice++) {
            __syncthreads();                // staging free / previous flush done
            if (myslice == slice) {
#pragma unroll
                for (int q = 0; q < 8; q++) {
                    int rc = q >> 2, np = q & 3;
                    int c   = ncol0 + np * 8 + (lane & 3) * 2;
                    int rl  = rc * 16 + (lane >> 2);       // 0..31 within slice
                    int fl  = c >> 4, nl = c & 15;
                    int p0  = fl * 64 + 16 + nl * 3 + tcomp;
                    int p1  = p0 + 3;
                    int sw  = (rl & 7) << 2;               // same for rl and rl+8
                    stg[rl * 512 + (p0 ^ sw)]       = acc[q][0];
                    stg[rl * 512 + (p1 ^ sw)]       = acc[q][1];
                    stg[(rl + 8) * 512 + (p0 ^ sw)] = acc[q][2];
                    stg[(rl + 8) * 512 + (p1 ^ sw)] = acc[q][3];
                }
            }
            __syncthreads();
            for (int i = tid; i < 4096; i += NTHREADS) {
                int xl = i >> 7, posq = (i & 127) << 2;
                float4 v;
                if ((posq & 63) < 16) v = make_float4(0.f, 0.f, 0.f, 0.f);  // scalar: exact cancel
                else                  v = *(float4*)&stg[xl * 512 + (posq ^ ((xl & 7) << 2))];
                *(float4*)&out[(size_t)(row0 + slice * 32 + xl) * 1024 + nh * 512 + posq] = v;
            }
        }
        if (nh == 0) {
            __syncthreads();
            load_B(smem, gCT_hi + 128 * 128, gCT_lo + 128 * 128, tid);  // C half 1
            __syncthreads();
        }
    }
}

// ---------------- launch ----------------
extern "C" void kernel_launch(void* const* d_in, const int* in_sizes, int n_in,
                              void* d_out, int out_size) {
    const float* x   = (const float*)d_in[0];
    const float* Wh0 = (const float*)d_in[1];
    const float* Wu0 = (const float*)d_in[2];
    const float* Wm0 = (const float*)d_in[3];
    const float* bm0 = (const float*)d_in[4];
    const float* Wh1 = (const float*)d_in[5];
    const float* Wu1 = (const float*)d_in[6];
    // d_in[7]=Wm1, d_in[8]=bm1, d_in[9]=W0 provably unused (scalar channel cancels)
    const float* W1  = (const float*)d_in[10];
    float* out = (float*)d_out;

    cudaFuncSetAttribute(fused, cudaFuncAttributeMaxDynamicSharedMemorySize, SMEM_BYTES);

    prep_T<<<S, S>>>(Wh1, Wu1);
    prep_C<<<S, MO>>>(W1);
    pack_w<<<384, 256>>>(Wh0, Wu0, Wm0);
    fused<<<NROWS / XR, NTHREADS, SMEM_BYTES>>>(x, bm0, out);
}